// round 1
// baseline (speedup 1.0000x reference)
#include <cuda_runtime.h>
#include <math.h>
#include <stdint.h>

#define BSZ 256
#define TT_ 512
#define XDIM 128
#define MDIM 128
#define ADIM 8
#define ZDIM 4
#define UDIM 9
#define KMIX 3
#define HL 50
#define HID 128
#define NROWS (BSZ*TT_)

// ---------------- scratch (static __device__ allocation; cudaMalloc is forbidden) ----
__device__ float g_buf1[NROWS*HID];
__device__ float g_buf2[NROWS*HID];
__device__ float g_a[NROWS*ADIM];
__device__ float g_alpha[NROWS*KMIX];
__device__ float g_mup[NROWS*ZDIM];
__device__ float g_muf[NROWS*ZDIM];
__device__ float g_Sigp[NROWS*ZDIM*ZDIM];
__device__ float g_Sigf[NROWS*ZDIM*ZDIM];
__device__ float g_J[NROWS*ZDIM*ZDIM];
__device__ float g_mus[NROWS*ZDIM];
__device__ float g_ahat[NROWS*ADIM];

// ---------------- activation ----------------
template<int ACT>
__device__ __forceinline__ float actf(float v){
    if (ACT == 1) return tanhf(v);
    if (ACT == 2) return 1.f/(1.f+expf(-v));
    return v;
}

// ---------------- generic fused SGEMM: C[M,128] = act(A[M,K] @ W[128,K]^T + bias) ----
// CONCAT: A is [A0(128 cols) | A1(128 cols)], K=256.
template<int ACT, bool CONCAT>
__global__ __launch_bounds__(256,2)
void sgemm128(const float* __restrict__ A0, const float* __restrict__ A1,
              const float* __restrict__ W, const float* __restrict__ bias,
              float* __restrict__ C, int K)
{
    __shared__ __align__(16) float As[16][132];
    __shared__ __align__(16) float Bsm[16][132];
    const int tid = threadIdx.x;
    const int row0 = blockIdx.x * 128;
    const int tx = tid & 15, ty = tid >> 4;
    float acc[8][8];
#pragma unroll
    for (int i=0;i<8;i++)
#pragma unroll
        for (int j=0;j<8;j++) acc[i][j]=0.f;

    for (int k0=0;k0<K;k0+=16){
#pragma unroll
        for (int q=tid;q<512;q+=256){
            int r=q>>2, kc=(q&3)<<2;
            const float* src;
            if (CONCAT){
                int gk=k0+kc;
                src = (gk<128)? (A0 + (size_t)(row0+r)*128 + gk)
                              : (A1 + (size_t)(row0+r)*128 + (gk-128));
            } else {
                src = A0 + (size_t)(row0+r)*K + k0 + kc;
            }
            float4 v = *(const float4*)src;
            As[kc+0][r]=v.x; As[kc+1][r]=v.y; As[kc+2][r]=v.z; As[kc+3][r]=v.w;
        }
#pragma unroll
        for (int q=tid;q<512;q+=256){
            int n=q>>2, kc=(q&3)<<2;
            float4 v = *(const float4*)(W + (size_t)n*K + k0 + kc);
            Bsm[kc+0][n]=v.x; Bsm[kc+1][n]=v.y; Bsm[kc+2][n]=v.z; Bsm[kc+3][n]=v.w;
        }
        __syncthreads();
#pragma unroll
        for (int k=0;k<16;k++){
            float4 a0=*(const float4*)&As[k][ty*8];
            float4 a1=*(const float4*)&As[k][ty*8+4];
            float4 b0=*(const float4*)&Bsm[k][tx*8];
            float4 b1=*(const float4*)&Bsm[k][tx*8+4];
            float av[8]={a0.x,a0.y,a0.z,a0.w,a1.x,a1.y,a1.z,a1.w};
            float bv[8]={b0.x,b0.y,b0.z,b0.w,b1.x,b1.y,b1.z,b1.w};
#pragma unroll
            for (int i=0;i<8;i++)
#pragma unroll
                for (int j=0;j<8;j++)
                    acc[i][j] += av[i]*bv[j];
        }
        __syncthreads();
    }
    float bn[8];
#pragma unroll
    for (int j=0;j<8;j++) bn[j]=bias[tx*8+j];
#pragma unroll
    for (int i=0;i<8;i++){
        size_t gr = (size_t)row0 + ty*8 + i;
        float4 o0, o1;
        o0.x=actf<ACT>(acc[i][0]+bn[0]); o0.y=actf<ACT>(acc[i][1]+bn[1]);
        o0.z=actf<ACT>(acc[i][2]+bn[2]); o0.w=actf<ACT>(acc[i][3]+bn[3]);
        o1.x=actf<ACT>(acc[i][4]+bn[4]); o1.y=actf<ACT>(acc[i][5]+bn[5]);
        o1.z=actf<ACT>(acc[i][6]+bn[6]); o1.w=actf<ACT>(acc[i][7]+bn[7]);
        *(float4*)&C[gr*128 + tx*8]     = o0;
        *(float4*)&C[gr*128 + tx*8 + 4] = o1;
    }
}

// ---------------- encoder layer 3: a = Y2 @ Wm^T + bm + eps  (N=8, K=128) ----------
__global__ __launch_bounds__(256)
void enc3_kernel(const float* __restrict__ Y2, const float* __restrict__ Wm,
                 const float* __restrict__ bm, const float* __restrict__ eps,
                 float* __restrict__ aout)
{
    __shared__ __align__(16) float sW[8][128];
    for (int i=threadIdx.x;i<1024;i+=256) sW[i>>7][i&127]=Wm[i];
    __syncthreads();
    int r = blockIdx.x*32 + (threadIdx.x>>3);
    int n = threadIdx.x&7;
    const float4* y = (const float4*)(Y2 + (size_t)r*128);
    const float4* w = (const float4*)&sW[n][0];
    float s=0.f;
#pragma unroll
    for (int k=0;k<32;k++){
        float4 yv=y[k], wv=w[k];
        s += yv.x*wv.x+yv.y*wv.y+yv.z*wv.z+yv.w*wv.w;
    }
    aout[(size_t)r*8+n] = s + bm[n] + eps[(size_t)r*8+n];
}

// ---------------- LSTM + alpha: block per batch, sequential over T ------------------
__global__ __launch_bounds__(256)
void lstm_kernel(const float* __restrict__ a, const float* __restrict__ a_init,
                 const float* __restrict__ Wih, const float* __restrict__ Whh,
                 const float* __restrict__ bih, const float* __restrict__ bhh,
                 const float* __restrict__ aW, const float* __restrict__ ab,
                 float* __restrict__ alpha)
{
    __shared__ float sh[HL];
    __shared__ float sx[ADIM];
    __shared__ float spre[200];
    __shared__ float saW[KMIX][HL];
    __shared__ float sab[KMIX];
    __shared__ float slog[KMIX];
    int tid=threadIdx.x; int b=blockIdx.x;
    float wih[8], whh[50], bsum=0.f, c=0.f;
    if (tid<200){
#pragma unroll
        for (int j=0;j<8;j++) wih[j]=Wih[tid*8+j];
#pragma unroll
        for (int j=0;j<50;j++) whh[j]=Whh[tid*50+j];
        bsum = bih[tid]+bhh[tid];
    }
    for (int i=tid;i<KMIX*HL;i+=256) saW[i/HL][i%HL]=aW[i];
    if (tid<KMIX) sab[tid]=ab[tid];
    if (tid<HL) sh[tid]=0.f;
    __syncthreads();
    for (int t=0;t<TT_;t++){
        if (tid<8) sx[tid] = (t==0)? a_init[tid] : a[((size_t)b*TT_ + t-1)*8 + tid];
        __syncthreads();
        if (tid<200){
            float p = bsum;
#pragma unroll
            for (int j=0;j<8;j++) p += wih[j]*sx[j];
#pragma unroll
            for (int j=0;j<50;j++) p += whh[j]*sh[j];
            spre[tid]=p;
        }
        __syncthreads();
        if (tid<50){
            float ig = 1.f/(1.f+expf(-spre[tid]));
            float fg = 1.f/(1.f+expf(-spre[50+tid]));
            float gg = tanhf(spre[100+tid]);
            float og = 1.f/(1.f+expf(-spre[150+tid]));
            c = fg*c + ig*gg;
            sh[tid] = og*tanhf(c);
        }
        __syncthreads();
        if (tid<96){
            int k=tid>>5, lane=tid&31;
            float s=0.f;
            for (int j=lane;j<HL;j+=32) s += saW[k][j]*sh[j];
#pragma unroll
            for (int off=16;off>0;off>>=1) s += __shfl_down_sync(0xffffffffu,s,off);
            if (lane==0) slog[k]=s+sab[k];
        }
        __syncthreads();
        if (tid<3){
            float l0=slog[0],l1=slog[1],l2=slog[2];
            float mx=fmaxf(l0,fmaxf(l1,l2));
            float e0=expf(l0-mx),e1=expf(l1-mx),e2=expf(l2-mx);
            float inv=1.f/(e0+e1+e2);
            float mine = (tid==0)?e0:((tid==1)?e1:e2);
            alpha[((size_t)b*TT_+t)*3+tid]=mine*inv;
        }
        // next iteration's first write (sx) is separated by the sync at loop top
        __syncthreads();
    }
}

// ---------------- Kalman forward: warp per batch element ---------------------------
#define O_AM   0
#define O_BM   16
#define O_CM   52
#define O_MU   84
#define O_SIG  88
#define O_MUP  104
#define O_SIGP 108
#define O_PC   124
#define O_SA   156
#define O_KG   284
#define O_RES  316
#define O_IKC  324
#define O_TT   340
#define O_AT   356
#define O_UT   364
#define O_AL   373
#define WSZ    384

__global__ __launch_bounds__(256)
void kf_forward(const float* __restrict__ alpha, const float* __restrict__ a,
                const float* __restrict__ a_init, const float* __restrict__ u_ext,
                const float* __restrict__ Ag, const float* __restrict__ Bg,
                const float* __restrict__ Cg,
                float* __restrict__ mu_p_g, float* __restrict__ Sig_p_g,
                float* __restrict__ mu_f_g, float* __restrict__ Sig_f_g)
{
    __shared__ float sA[48], sB[108], sC[96];
    __shared__ float wsm[8][WSZ];
    int w = threadIdx.x>>5, lane = threadIdx.x&31;
    int b = blockIdx.x*8 + w;
    for (int i=threadIdx.x;i<48;i+=256) sA[i]=Ag[i];
    for (int i=threadIdx.x;i<108;i+=256) sB[i]=Bg[i];
    for (int i=threadIdx.x;i<96;i+=256) sC[i]=Cg[i];
    __syncthreads();
    float* s = wsm[w];

    for (int t=0;t<TT_;t++){
        size_t bt = (size_t)b*TT_ + t;
        if (lane<3) s[O_AL+lane]=alpha[bt*3+lane];
        if (lane>=4 && lane<12) s[O_AT+lane-4]=a[bt*8+lane-4];
        if (lane>=12 && lane<20) s[O_UT+lane-12] = (t==0)? a_init[lane-12] : a[(bt-1)*8+lane-12];
        if (lane==20) s[O_UT+8]=u_ext[bt];
        __syncwarp();
        float al0=s[O_AL+0], al1=s[O_AL+1], al2=s[O_AL+2];
        for (int f=lane; f<84; f+=32){
            if (f<16)      s[O_AM+f]   = al0*sA[f]      + al1*sA[16+f]    + al2*sA[32+f];
            else if (f<52){int j=f-16; s[O_BM+j] = al0*sB[j] + al1*sB[36+j] + al2*sB[72+j];}
            else          {int j=f-52; s[O_CM+j] = al0*sC[j] + al1*sC[32+j] + al2*sC[64+j];}
        }
        __syncwarp();
        if (t==0){
            if (lane<4) s[O_MUP+lane]=0.f;
            if (lane<16){int i=lane>>2, j=lane&3; s[O_SIGP+lane]=(i==j)?20.f:0.f;}
        } else {
            if (lane<4){
                float v=0.f;
#pragma unroll
                for (int j=0;j<4;j++) v += s[O_AM+lane*4+j]*s[O_MU+j];
#pragma unroll
                for (int j=0;j<9;j++) v += s[O_BM+lane*9+j]*s[O_UT+j];
                s[O_MUP+lane]=v;
            }
            if (lane<16){
                int i=lane>>2, j=lane&3; float v=0.f;
#pragma unroll
                for (int k=0;k<4;k++) v += s[O_AM+i*4+k]*s[O_SIG+k*4+j];
                s[O_TT+lane]=v;
            }
            __syncwarp();
            if (lane<16){
                int i=lane>>2, j=lane&3;
                float v=(i==j)?0.08f:0.f;
#pragma unroll
                for (int k=0;k<4;k++) v += s[O_TT+i*4+k]*s[O_AM+j*4+k];
                s[O_SIGP+lane]=v;
            }
        }
        __syncwarp();
        { // PC = Sig_p C^T : 4x8
            int i=lane>>3, cc=lane&7; float v=0.f;
#pragma unroll
            for (int k=0;k<4;k++) v += s[O_SIGP+i*4+k]*s[O_CM+cc*4+k];
            s[O_PC+i*8+cc]=v;
        }
        __syncwarp();
        for (int f=lane; f<128; f+=32){ // augmented [S | I]
            int r=f>>4, cc=f&15; float v;
            if (cc<8){
                v=(r==cc)?0.03f:0.f;
#pragma unroll
                for (int k=0;k<4;k++) v += s[O_CM+r*4+k]*s[O_PC+k*8+cc];
            } else v = ((cc-8)==r)?1.f:0.f;
            s[O_SA+f]=v;
        }
        __syncwarp();
        // Gauss-Jordan on 8x16 (S is SPD: no pivoting)
        for (int p=0;p<8;p++){
            float piv = s[O_SA+p*16+p];
            __syncwarp();
            float ip = 1.f/piv;
            if (lane<16) s[O_SA+p*16+lane] *= ip;
            __syncwarp();
            int cc=lane&15, rb=lane>>4;
            float pr = s[O_SA+p*16+cc];
            float fac[4];
#pragma unroll
            for (int q=0;q<4;q++) fac[q]=s[O_SA+(rb+2*q)*16+p];
            __syncwarp();
#pragma unroll
            for (int q=0;q<4;q++){
                int r=rb+2*q;
                if (r!=p) s[O_SA+r*16+cc] -= fac[q]*pr;
            }
            __syncwarp();
        }
        { // Kg = PC @ Sinv : 4x8
            int i=lane>>3, cc=lane&7; float v=0.f;
#pragma unroll
            for (int k=0;k<8;k++) v += s[O_PC+i*8+k]*s[O_SA+k*16+8+cc];
            s[O_KG+i*8+cc]=v;
        }
        if (lane<8){
            float v=s[O_AT+lane];
#pragma unroll
            for (int k=0;k<4;k++) v -= s[O_CM+lane*4+k]*s[O_MUP+k];
            s[O_RES+lane]=v;
        }
        __syncwarp();
        if (lane<4){
            float v=s[O_MUP+lane];
#pragma unroll
            for (int cc=0;cc<8;cc++) v += s[O_KG+lane*8+cc]*s[O_RES+cc];
            s[O_MU+lane]=v;
        }
        if (lane>=8 && lane<24){
            int l=lane-8; int i=l>>2, j=l&3;
            float v=(i==j)?1.f:0.f;
#pragma unroll
            for (int cc=0;cc<8;cc++) v -= s[O_KG+i*8+cc]*s[O_CM+cc*4+j];
            s[O_IKC+l]=v;
        }
        __syncwarp();
        if (lane<16){
            int i=lane>>2, j=lane&3; float v=0.f;
#pragma unroll
            for (int k=0;k<4;k++) v += s[O_IKC+i*4+k]*s[O_SIGP+k*4+j];
            s[O_TT+lane]=v;
        }
        __syncwarp();
        if (lane<16){
            int i=lane>>2, j=lane&3; float v=0.f;
#pragma unroll
            for (int k=0;k<4;k++) v += s[O_TT+i*4+k]*s[O_IKC+j*4+k];
            float kk=0.f;
#pragma unroll
            for (int cc=0;cc<8;cc++) kk += s[O_KG+i*8+cc]*s[O_KG+j*8+cc];
            s[O_SIG+lane]=v+0.03f*kk;
        }
        __syncwarp();
        if (lane<16) Sig_f_g[bt*16+lane]=s[O_SIG+lane];
        else         Sig_p_g[bt*16+lane-16]=s[O_SIGP+lane-16];
        if (lane<4)             mu_f_g[bt*4+lane]  =s[O_MU+lane];
        else if (lane<8)        mu_p_g[bt*4+lane-4]=s[O_MUP+lane-4];
        __syncwarp();
    }
}

// ---------------- 4x4 inverse (cofactors) ------------------------------------------
__device__ __forceinline__ void inv4(const float m[16], float inv[16]){
    inv[0]  =  m[5]*m[10]*m[15]-m[5]*m[11]*m[14]-m[9]*m[6]*m[15]+m[9]*m[7]*m[14]+m[13]*m[6]*m[11]-m[13]*m[7]*m[10];
    inv[4]  = -m[4]*m[10]*m[15]+m[4]*m[11]*m[14]+m[8]*m[6]*m[15]-m[8]*m[7]*m[14]-m[12]*m[6]*m[11]+m[12]*m[7]*m[10];
    inv[8]  =  m[4]*m[9]*m[15]-m[4]*m[11]*m[13]-m[8]*m[5]*m[15]+m[8]*m[7]*m[13]+m[12]*m[5]*m[11]-m[12]*m[7]*m[9];
    inv[12] = -m[4]*m[9]*m[14]+m[4]*m[10]*m[13]+m[8]*m[5]*m[14]-m[8]*m[6]*m[13]-m[12]*m[5]*m[10]+m[12]*m[6]*m[9];
    inv[1]  = -m[1]*m[10]*m[15]+m[1]*m[11]*m[14]+m[9]*m[2]*m[15]-m[9]*m[3]*m[14]-m[13]*m[2]*m[11]+m[13]*m[3]*m[10];
    inv[5]  =  m[0]*m[10]*m[15]-m[0]*m[11]*m[14]-m[8]*m[2]*m[15]+m[8]*m[3]*m[14]+m[12]*m[2]*m[11]-m[12]*m[3]*m[10];
    inv[9]  = -m[0]*m[9]*m[15]+m[0]*m[11]*m[13]+m[8]*m[1]*m[15]-m[8]*m[3]*m[13]-m[12]*m[1]*m[11]+m[12]*m[3]*m[9];
    inv[13] =  m[0]*m[9]*m[14]-m[0]*m[10]*m[13]-m[8]*m[1]*m[14]+m[8]*m[2]*m[13]+m[12]*m[1]*m[10]-m[12]*m[2]*m[9];
    inv[2]  =  m[1]*m[6]*m[15]-m[1]*m[7]*m[14]-m[5]*m[2]*m[15]+m[5]*m[3]*m[14]+m[13]*m[2]*m[7]-m[13]*m[3]*m[6];
    inv[6]  = -m[0]*m[6]*m[15]+m[0]*m[7]*m[14]+m[4]*m[2]*m[15]-m[4]*m[3]*m[14]-m[12]*m[2]*m[7]+m[12]*m[3]*m[6];
    inv[10] =  m[0]*m[5]*m[15]-m[0]*m[7]*m[13]-m[4]*m[1]*m[15]+m[4]*m[3]*m[13]+m[12]*m[1]*m[7]-m[12]*m[3]*m[5];
    inv[14] = -m[0]*m[5]*m[14]+m[0]*m[6]*m[13]+m[4]*m[1]*m[14]-m[4]*m[2]*m[13]-m[12]*m[1]*m[6]+m[12]*m[2]*m[5];
    inv[3]  = -m[1]*m[6]*m[11]+m[1]*m[7]*m[10]+m[5]*m[2]*m[11]-m[5]*m[3]*m[10]-m[9]*m[2]*m[7]+m[9]*m[3]*m[6];
    inv[7]  =  m[0]*m[6]*m[11]-m[0]*m[7]*m[10]-m[4]*m[2]*m[11]+m[4]*m[3]*m[10]+m[8]*m[2]*m[7]-m[8]*m[3]*m[6];
    inv[11] = -m[0]*m[5]*m[11]+m[0]*m[7]*m[9]+m[4]*m[1]*m[11]-m[4]*m[3]*m[9]-m[8]*m[1]*m[7]+m[8]*m[3]*m[5];
    inv[15] =  m[0]*m[5]*m[10]-m[0]*m[6]*m[9]-m[4]*m[1]*m[10]+m[4]*m[2]*m[9]+m[8]*m[1]*m[6]-m[8]*m[2]*m[5];
    float det = m[0]*inv[0]+m[1]*inv[4]+m[2]*inv[8]+m[3]*inv[12];
    float id = 1.f/det;
#pragma unroll
    for (int i=0;i<16;i++) inv[i]*=id;
}

// ---------------- smoother gains J_t = Sig_f[t] A[t+1]^T inv(Sig_p[t+1]) (parallel) -
__global__ void jmat_kernel(const float* __restrict__ alpha, const float* __restrict__ Sig_f,
                            const float* __restrict__ Sig_p, const float* __restrict__ Ag,
                            float* __restrict__ Jg)
{
    int idx = blockIdx.x*blockDim.x + threadIdx.x;
    if (idx >= BSZ*(TT_-1)) return;
    int b = idx/(TT_-1), t = idx%(TT_-1);
    size_t bt = (size_t)b*TT_ + t;
    float a0=alpha[(bt+1)*3+0], a1=alpha[(bt+1)*3+1], a2=alpha[(bt+1)*3+2];
    float Am[16], Sf[16], Sp[16], Pi[16], G[16];
#pragma unroll
    for (int i=0;i<16;i++) Am[i] = a0*Ag[i]+a1*Ag[16+i]+a2*Ag[32+i];
#pragma unroll
    for (int i=0;i<16;i++) Sf[i] = Sig_f[bt*16+i];
#pragma unroll
    for (int i=0;i<16;i++) Sp[i] = Sig_p[(bt+1)*16+i];
    inv4(Sp, Pi);
#pragma unroll
    for (int i=0;i<4;i++)
#pragma unroll
        for (int k=0;k<4;k++){
            float v=0.f;
#pragma unroll
            for (int j=0;j<4;j++) v += Sf[i*4+j]*Am[k*4+j];
            G[i*4+k]=v;
        }
#pragma unroll
    for (int i=0;i<4;i++)
#pragma unroll
        for (int l=0;l<4;l++){
            float v=0.f;
#pragma unroll
            for (int k=0;k<4;k++) v += G[i*4+k]*Pi[k*4+l];
            Jg[bt*16+i*4+l]=v;
        }
}

// ---------------- backward mu_smooth recursion (4 lanes per batch) ------------------
__global__ void smooth_kernel(const float* __restrict__ mu_f, const float* __restrict__ mu_p,
                              const float* __restrict__ Jg, float* __restrict__ mus)
{
    int g = blockIdx.x*32 + (threadIdx.x>>2);
    int i = threadIdx.x & 3;
    if (g >= BSZ) return;
    size_t base = (size_t)g*TT_;
    float v = mu_f[(base+TT_-1)*4 + i];
    mus[(base+TT_-1)*4 + i] = v;
    unsigned gb = threadIdx.x & ~3u;
    for (int t=TT_-2; t>=0; t--){
        float4 Jr = *(const float4*)&Jg[(base+t)*16 + i*4];
        float mf = mu_f[(base+t)*4+i];
        float mp = mu_p[(base+t+1)*4+i];
        float mi = v - mp;
        float m0=__shfl_sync(0xffffffffu, mi, gb+0);
        float m1=__shfl_sync(0xffffffffu, mi, gb+1);
        float m2=__shfl_sync(0xffffffffu, mi, gb+2);
        float m3=__shfl_sync(0xffffffffu, mi, gb+3);
        v = mf + Jr.x*m0 + Jr.y*m1 + Jr.z*m2 + Jr.w*m3;
        mus[(base+t)*4+i]=v;
    }
}

// ---------------- a_hat = C_mix mu_smooth -------------------------------------------
__global__ void ahat_kernel(const float* __restrict__ alpha, const float* __restrict__ mus,
                            const float* __restrict__ Cg, float* __restrict__ ahat)
{
    int idx = blockIdx.x*blockDim.x + threadIdx.x;
    if (idx >= NROWS) return;
    float a0=alpha[(size_t)idx*3+0], a1=alpha[(size_t)idx*3+1], a2=alpha[(size_t)idx*3+2];
    float4 mu = *(const float4*)&mus[(size_t)idx*4];
    float mv[4]={mu.x,mu.y,mu.z,mu.w};
#pragma unroll
    for (int r=0;r<8;r++){
        float v=0.f;
#pragma unroll
        for (int j=0;j<4;j++){
            float cm = a0*__ldg(&Cg[r*4+j]) + a1*__ldg(&Cg[32+r*4+j]) + a2*__ldg(&Cg[64+r*4+j]);
            v += cm*mv[j];
        }
        ahat[(size_t)idx*8+r]=v;
    }
}

// ---------------- decoder layer 1: d1 = tanh(ahat @ W^T + b) (K=8) ------------------
__global__ __launch_bounds__(256)
void dec1_kernel(const float* __restrict__ ahat, const float* __restrict__ W,
                 const float* __restrict__ bvec, float* __restrict__ out)
{
    __shared__ float sa[16][8];
    int tid = threadIdx.x;
    int r0 = blockIdx.x*16;
    if (tid<128) sa[tid>>3][tid&7] = ahat[(size_t)r0*8 + tid];
    int n = tid & 127;
    float w[8];
#pragma unroll
    for (int j=0;j<8;j++) w[j]=W[n*8+j];
    float bb=bvec[n];
    __syncthreads();
    int half = tid>>7;
#pragma unroll
    for (int q=0;q<8;q++){
        int rl = half*8+q;
        float s=bb;
#pragma unroll
        for (int j=0;j<8;j++) s += sa[rl][j]*w[j];
        out[(size_t)(r0+rl)*128 + n] = tanhf(s);
    }
}

// ---------------- launcher ----------------------------------------------------------
extern "C" void kernel_launch(void* const* d_in, const int* in_sizes, int n_in,
                              void* d_out, int out_size)
{
    const float* x       = (const float*)d_in[0];
    const float* m       = (const float*)d_in[1];
    const float* u_ext   = (const float*)d_in[2];
    const float* eps     = (const float*)d_in[3];
    const float* enc_W1  = (const float*)d_in[4];
    const float* enc_b1  = (const float*)d_in[5];
    const float* enc_W2  = (const float*)d_in[6];
    const float* enc_b2  = (const float*)d_in[7];
    const float* W_mean  = (const float*)d_in[8];
    const float* b_mean  = (const float*)d_in[9];
    const float* Amat    = (const float*)d_in[10];
    const float* Bmat    = (const float*)d_in[11];
    const float* Cmat    = (const float*)d_in[12];
    const float* a_init  = (const float*)d_in[13];
    const float* lstm_Wih= (const float*)d_in[14];
    const float* lstm_Whh= (const float*)d_in[15];
    const float* lstm_bih= (const float*)d_in[16];
    const float* lstm_bhh= (const float*)d_in[17];
    const float* alpha_W = (const float*)d_in[18];
    const float* alpha_b = (const float*)d_in[19];
    const float* dec_W1  = (const float*)d_in[20];
    const float* dec_b1  = (const float*)d_in[21];
    const float* dec_W2  = (const float*)d_in[22];
    const float* dec_b2  = (const float*)d_in[23];
    const float* gen_W   = (const float*)d_in[24];
    const float* gen_b   = (const float*)d_in[25];

    float *p_buf1,*p_buf2,*p_a,*p_alpha,*p_mup,*p_muf,*p_Sigp,*p_Sigf,*p_J,*p_mus,*p_ahat;
    cudaGetSymbolAddress((void**)&p_buf1,  g_buf1);
    cudaGetSymbolAddress((void**)&p_buf2,  g_buf2);
    cudaGetSymbolAddress((void**)&p_a,     g_a);
    cudaGetSymbolAddress((void**)&p_alpha, g_alpha);
    cudaGetSymbolAddress((void**)&p_mup,   g_mup);
    cudaGetSymbolAddress((void**)&p_muf,   g_muf);
    cudaGetSymbolAddress((void**)&p_Sigp,  g_Sigp);
    cudaGetSymbolAddress((void**)&p_Sigf,  g_Sigf);
    cudaGetSymbolAddress((void**)&p_J,     g_J);
    cudaGetSymbolAddress((void**)&p_mus,   g_mus);
    cudaGetSymbolAddress((void**)&p_ahat,  g_ahat);

    // encoder
    sgemm128<1,true ><<<NROWS/128,256>>>(x, m, enc_W1, enc_b1, p_buf1, 256);
    sgemm128<1,false><<<NROWS/128,256>>>(p_buf1, nullptr, enc_W2, enc_b2, p_buf2, 128);
    enc3_kernel<<<NROWS/32,256>>>(p_buf2, W_mean, b_mean, eps, p_a);
    // LSTM -> alpha
    lstm_kernel<<<BSZ,256>>>(p_a, a_init, lstm_Wih, lstm_Whh, lstm_bih, lstm_bhh,
                             alpha_W, alpha_b, p_alpha);
    // Kalman forward
    kf_forward<<<BSZ/8,256>>>(p_alpha, p_a, a_init, u_ext, Amat, Bmat, Cmat,
                              p_mup, p_Sigp, p_muf, p_Sigf);
    // smoother gains (parallel) + backward mu recursion
    jmat_kernel<<<(BSZ*(TT_-1)+255)/256,256>>>(p_alpha, p_Sigf, p_Sigp, Amat, p_J);
    smooth_kernel<<<8,128>>>(p_muf, p_mup, p_J, p_mus);
    ahat_kernel<<<NROWS/256,256>>>(p_alpha, p_mus, Cmat, p_ahat);
    // decoder
    dec1_kernel<<<NROWS/16,256>>>(p_ahat, dec_W1, dec_b1, p_buf1);
    sgemm128<1,false><<<NROWS/128,256>>>(p_buf1, nullptr, dec_W2, dec_b2, p_buf2, 128);
    sgemm128<2,false><<<NROWS/128,256>>>(p_buf2, nullptr, gen_W, gen_b, (float*)d_out, 128);
    (void)in_sizes; (void)n_in; (void)out_size;
}

// round 2
// speedup vs baseline: 1.8225x; 1.8225x over previous
#include <cuda_runtime.h>
#include <math.h>
#include <stdint.h>

#define BSZ 256
#define TT_ 512
#define ADIM 8
#define ZDIM 4
#define KMIX 3
#define HL 50
#define HID 128
#define NROWS (BSZ*TT_)

// ---------------- scratch (static __device__; cudaMalloc forbidden) ----------------
__device__ float g_buf1[NROWS*HID];
__device__ float g_buf2[NROWS*HID];
__device__ float g_a[NROWS*ADIM];
__device__ float g_alpha[NROWS*KMIX];
__device__ float g_mup[NROWS*ZDIM];
__device__ float g_muf[NROWS*ZDIM];
__device__ float g_J[NROWS*ZDIM*ZDIM];
__device__ float g_mus[NROWS*ZDIM];
__device__ float g_ahat[NROWS*ADIM];

// ---------------- activation ----------------
template<int ACT>
__device__ __forceinline__ float actf(float v){
    if (ACT == 1) return tanhf(v);
    if (ACT == 2) return 1.f/(1.f+expf(-v));
    return v;
}

// ---------------- generic fused SGEMM: C[M,128] = act(A[M,K] @ W[128,K]^T + bias) ----
template<int ACT, bool CONCAT>
__global__ __launch_bounds__(256,2)
void sgemm128(const float* __restrict__ A0, const float* __restrict__ A1,
              const float* __restrict__ W, const float* __restrict__ bias,
              float* __restrict__ C, int K)
{
    __shared__ __align__(16) float As[16][132];
    __shared__ __align__(16) float Bsm[16][132];
    const int tid = threadIdx.x;
    const int row0 = blockIdx.x * 128;
    const int tx = tid & 15, ty = tid >> 4;
    float acc[8][8];
#pragma unroll
    for (int i=0;i<8;i++)
#pragma unroll
        for (int j=0;j<8;j++) acc[i][j]=0.f;

    for (int k0=0;k0<K;k0+=16){
#pragma unroll
        for (int q=tid;q<512;q+=256){
            int r=q>>2, kc=(q&3)<<2;
            const float* src;
            if (CONCAT){
                int gk=k0+kc;
                src = (gk<128)? (A0 + (size_t)(row0+r)*128 + gk)
                              : (A1 + (size_t)(row0+r)*128 + (gk-128));
            } else {
                src = A0 + (size_t)(row0+r)*K + k0 + kc;
            }
            float4 v = *(const float4*)src;
            As[kc+0][r]=v.x; As[kc+1][r]=v.y; As[kc+2][r]=v.z; As[kc+3][r]=v.w;
        }
#pragma unroll
        for (int q=tid;q<512;q+=256){
            int n=q>>2, kc=(q&3)<<2;
            float4 v = *(const float4*)(W + (size_t)n*K + k0 + kc);
            Bsm[kc+0][n]=v.x; Bsm[kc+1][n]=v.y; Bsm[kc+2][n]=v.z; Bsm[kc+3][n]=v.w;
        }
        __syncthreads();
#pragma unroll
        for (int k=0;k<16;k++){
            float4 a0=*(const float4*)&As[k][ty*8];
            float4 a1=*(const float4*)&As[k][ty*8+4];
            float4 b0=*(const float4*)&Bsm[k][tx*8];
            float4 b1=*(const float4*)&Bsm[k][tx*8+4];
            float av[8]={a0.x,a0.y,a0.z,a0.w,a1.x,a1.y,a1.z,a1.w};
            float bv[8]={b0.x,b0.y,b0.z,b0.w,b1.x,b1.y,b1.z,b1.w};
#pragma unroll
            for (int i=0;i<8;i++)
#pragma unroll
                for (int j=0;j<8;j++)
                    acc[i][j] += av[i]*bv[j];
        }
        __syncthreads();
    }
    float bn[8];
#pragma unroll
    for (int j=0;j<8;j++) bn[j]=bias[tx*8+j];
#pragma unroll
    for (int i=0;i<8;i++){
        size_t gr = (size_t)row0 + ty*8 + i;
        float4 o0, o1;
        o0.x=actf<ACT>(acc[i][0]+bn[0]); o0.y=actf<ACT>(acc[i][1]+bn[1]);
        o0.z=actf<ACT>(acc[i][2]+bn[2]); o0.w=actf<ACT>(acc[i][3]+bn[3]);
        o1.x=actf<ACT>(acc[i][4]+bn[4]); o1.y=actf<ACT>(acc[i][5]+bn[5]);
        o1.z=actf<ACT>(acc[i][6]+bn[6]); o1.w=actf<ACT>(acc[i][7]+bn[7]);
        *(float4*)&C[gr*128 + tx*8]     = o0;
        *(float4*)&C[gr*128 + tx*8 + 4] = o1;
    }
}

// ---------------- encoder layer 3: a = Y2 @ Wm^T + bm + eps  (N=8, K=128) ----------
__global__ __launch_bounds__(256)
void enc3_kernel(const float* __restrict__ Y2, const float* __restrict__ Wm,
                 const float* __restrict__ bm, const float* __restrict__ eps,
                 float* __restrict__ aout)
{
    __shared__ __align__(16) float sW[8][128];
    for (int i=threadIdx.x;i<1024;i+=256) sW[i>>7][i&127]=Wm[i];
    __syncthreads();
    int r = blockIdx.x*32 + (threadIdx.x>>3);
    int n = threadIdx.x&7;
    const float4* y = (const float4*)(Y2 + (size_t)r*128);
    const float4* w = (const float4*)&sW[n][0];
    float s=0.f;
#pragma unroll
    for (int k=0;k<32;k++){
        float4 yv=y[k], wv=w[k];
        s += yv.x*wv.x+yv.y*wv.y+yv.z*wv.z+yv.w*wv.w;
    }
    aout[(size_t)r*8+n] = s + bm[n] + eps[(size_t)r*8+n];
}

// ---------------- LSTM + alpha: block per batch, 2 syncs/step, pipelined alpha ------
__global__ __launch_bounds__(256)
void lstm_kernel(const float* __restrict__ a, const float* __restrict__ a_init,
                 const float* __restrict__ Wih, const float* __restrict__ Whh,
                 const float* __restrict__ bih, const float* __restrict__ bhh,
                 const float* __restrict__ aW, const float* __restrict__ ab,
                 float* __restrict__ alpha)
{
    __shared__ __align__(16) float4 shv[13];      // h, padded to 52
    __shared__ __align__(16) float4 sxv[2][2];    // x_t, double buffered (8)
    __shared__ float spre[200];
    __shared__ __align__(16) float4 saWv[3][13];
    __shared__ float sab_s[3];
    __shared__ float slog[3];
    int tid=threadIdx.x; int b=blockIdx.x;

    float wih[8], whh[52], bsum=0.f, c=0.f;
    if (tid<200){
#pragma unroll
        for (int j=0;j<8;j++) wih[j]=Wih[tid*8+j];
#pragma unroll
        for (int j=0;j<50;j++) whh[j]=Whh[tid*50+j];
        whh[50]=0.f; whh[51]=0.f;
        bsum = bih[tid]+bhh[tid];
    }
    for (int i=tid;i<3*52;i+=256){
        int row=i/52, col=i%52;
        ((float*)saWv)[i] = (col<50)? aW[row*50+col] : 0.f;
    }
    if (tid<3) sab_s[tid]=ab[tid];
    for (int i=tid;i<52;i+=256) ((float*)shv)[i]=0.f;
    if (tid<8) ((float*)sxv)[tid]=a_init[tid];    // sxv[0] = a_init
    __syncthreads();

    for (int t=0;t<TT_;t++){
        int pb = t&1;
        // ---- P1 ----
        if (tid<200){
            const float4* xv = sxv[pb];
            float4 x0=xv[0], x1=xv[1];
            float a0 = bsum + wih[0]*x0.x + wih[4]*x1.x;
            float a1 = wih[1]*x0.y + wih[5]*x1.y;
            float a2 = wih[2]*x0.z + wih[6]*x1.z;
            float a3 = wih[3]*x0.w + wih[7]*x1.w;
#pragma unroll
            for (int q=0;q<13;q++){
                float4 hv=shv[q];
                a0 += whh[4*q+0]*hv.x;
                a1 += whh[4*q+1]*hv.y;
                a2 += whh[4*q+2]*hv.z;
                a3 += whh[4*q+3]*hv.w;
            }
            spre[tid]=(a0+a1)+(a2+a3);
        } else if (tid>=224 && tid<227){
            if (t>0){
                int k=tid-224;
                float a0=0,a1=0,a2=0,a3=0;
#pragma unroll
                for (int q=0;q<13;q++){
                    float4 wv=saWv[k][q], hv=shv[q];
                    a0+=wv.x*hv.x; a1+=wv.y*hv.y; a2+=wv.z*hv.z; a3+=wv.w*hv.w;
                }
                slog[k]=(a0+a1)+(a2+a3)+sab_s[k];
            }
        } else if (tid>=232 && tid<240){
            if (t<TT_-1)
                ((float*)sxv[pb^1])[tid-232] = a[((size_t)b*TT_+t)*8 + (tid-232)];
        }
        __syncthreads();
        // ---- P2 ----
        if (tid<50){
            float pi=spre[tid], pf=spre[50+tid], pg=spre[100+tid], po=spre[150+tid];
            float ig=1.f/(1.f+expf(-pi));
            float fg=1.f/(1.f+expf(-pf));
            float gg=tanhf(pg);
            float og=1.f/(1.f+expf(-po));
            c = fg*c + ig*gg;
            ((float*)shv)[tid] = og*tanhf(c);
        } else if (tid>=224 && tid<227 && t>0){
            int k=tid-224;
            float l0=slog[0],l1=slog[1],l2=slog[2];
            float mx=fmaxf(l0,fmaxf(l1,l2));
            float e0=expf(l0-mx),e1=expf(l1-mx),e2=expf(l2-mx);
            float inv=1.f/(e0+e1+e2);
            float mine=(k==0)?e0:((k==1)?e1:e2);
            alpha[((size_t)b*TT_+t-1)*3+k]=mine*inv;
        }
        __syncthreads();
    }
    // final alpha (t = T-1) from h_{T-1}
    if (tid>=224 && tid<227){
        int k=tid-224;
        float lg[3];
#pragma unroll
        for (int kk=0;kk<3;kk++){
            float a0=0,a1=0,a2=0,a3=0;
#pragma unroll
            for (int q=0;q<13;q++){
                float4 wv=saWv[kk][q], hv=shv[q];
                a0+=wv.x*hv.x; a1+=wv.y*hv.y; a2+=wv.z*hv.z; a3+=wv.w*hv.w;
            }
            lg[kk]=(a0+a1)+(a2+a3)+sab_s[kk];
        }
        float mx=fmaxf(lg[0],fmaxf(lg[1],lg[2]));
        float e0=expf(lg[0]-mx),e1=expf(lg[1]-mx),e2=expf(lg[2]-mx);
        float inv=1.f/(e0+e1+e2);
        float mine=(k==0)?e0:((k==1)?e1:e2);
        alpha[((size_t)b*TT_+TT_-1)*3+k]=mine*inv;
    }
}

// ---------------- 4x4 determinant + adjugate helpers --------------------------------
__device__ __forceinline__ float det4s(const float* m){
    float m00=m[0],m01=m[1],m02=m[2],m03=m[3];
    float m10=m[4],m11=m[5],m12=m[6],m13=m[7];
    float m20=m[8],m21=m[9],m22=m[10],m23=m[11];
    float m30=m[12],m31=m[13],m32=m[14],m33=m[15];
    return m00*(m11*(m22*m33-m23*m32)-m12*(m21*m33-m23*m31)+m13*(m21*m32-m22*m31))
         - m01*(m10*(m22*m33-m23*m32)-m12*(m20*m33-m23*m30)+m13*(m20*m32-m22*m30))
         + m02*(m10*(m21*m33-m23*m31)-m11*(m20*m33-m23*m30)+m13*(m20*m31-m21*m30))
         - m03*(m10*(m21*m32-m22*m31)-m11*(m20*m32-m22*m30)+m12*(m20*m31-m21*m30));
}

// adjugate entry for inverse layout: INV[r*4+c] = cof(c,r);  inv = adj * (1/det)
__device__ __forceinline__ float adj_entry(const float* m, int l){
    int r=l>>2, c=l&3;
    int rr[3], cc[3];
    int p=0;
#pragma unroll
    for (int k=0;k<4;k++) if (k!=c) rr[p++]=k;
    p=0;
#pragma unroll
    for (int k=0;k<4;k++) if (k!=r) cc[p++]=k;
    float a00=m[rr[0]*4+cc[0]], a01=m[rr[0]*4+cc[1]], a02=m[rr[0]*4+cc[2]];
    float a10=m[rr[1]*4+cc[0]], a11=m[rr[1]*4+cc[1]], a12=m[rr[1]*4+cc[2]];
    float a20=m[rr[2]*4+cc[0]], a21=m[rr[2]*4+cc[1]], a22=m[rr[2]*4+cc[2]];
    float d = a00*(a11*a22-a12*a21) - a01*(a10*a22-a12*a20) + a02*(a10*a21-a11*a20);
    return ((r+c)&1)? -d : d;
}

// ---------------- Kalman forward + smoother gains (Woodbury, 11 phases/step) --------
#define KO_AM   0
#define KO_BM   16
#define KO_CM   52
#define KO_SIGP 84
#define KO_PADJ 100
#define KO_MM   116
#define KO_MADJ 132
#define KO_KG   148
#define KO_IKC  180
#define KO_T    196
#define KO_T2   212
#define KO_SIG  228
#define KO_MU   244
#define KO_MUP  248
#define KO_RES  252
#define KO_AT   260
#define KO_UT   268
#define KO_AL   277
#define KO_DET  280
#define KWSZ    288

__global__ __launch_bounds__(64)
void kf_forward(const float* __restrict__ alpha, const float* __restrict__ a,
                const float* __restrict__ a_init, const float* __restrict__ u_ext,
                const float* __restrict__ Ag, const float* __restrict__ Bg,
                const float* __restrict__ Cg,
                float* __restrict__ mu_p_g, float* __restrict__ mu_f_g,
                float* __restrict__ Jg)
{
    __shared__ float sA[48], sB[108], sC[96];
    __shared__ float wsm[2][KWSZ];
    const float qn=0.08f, rn=0.03f, ir=1.f/0.03f;
    int w = threadIdx.x>>5, ln = threadIdx.x&31;
    int b = blockIdx.x*2 + w;
    for (int i=threadIdx.x;i<48;i+=64) sA[i]=Ag[i];
    for (int i=threadIdx.x;i<108;i+=64) sB[i]=Bg[i];
    for (int i=threadIdx.x;i<96;i+=64) sC[i]=Cg[i];
    __syncthreads();
    float* s = wsm[w];

    // prefetch t=0 inputs
    float r_al=0.f, r_a=0.f, r_u=0.f, r_ap=0.f;
    if (ln<3)            r_al = alpha[(size_t)b*TT_*3 + ln];
    if (ln>=4 && ln<12){ r_a  = a[(size_t)b*TT_*8 + (ln-4)]; r_ap = a_init[ln-4]; }
    if (ln==12)          r_u  = u_ext[(size_t)b*TT_];

    for (int t=0;t<TT_;t++){
        size_t bt = (size_t)b*TT_ + t;
        // ---- P0: publish step inputs ----
        if (ln<3) s[KO_AL+ln]=r_al;
        if (ln>=4 && ln<12){ s[KO_AT+ln-4]=r_a; s[KO_UT+ln-4]=r_ap; r_ap=r_a; }
        if (ln==12) s[KO_UT+8]=r_u;
        __syncwarp();
        // prefetch t+1 (hidden behind this step's compute)
        if (t+1<TT_){
            if (ln<3)            r_al = alpha[(bt+1)*3+ln];
            if (ln>=4 && ln<12)  r_a  = a[(bt+1)*8 + (ln-4)];
            if (ln==12)          r_u  = u_ext[bt+1];
        }
        // ---- P1: mix Am/Bm/Cm ----
        float al0=s[KO_AL], al1=s[KO_AL+1], al2=s[KO_AL+2];
        for (int f=ln; f<84; f+=32){
            if (f<16)      s[KO_AM+f] = al0*sA[f] + al1*sA[16+f] + al2*sA[32+f];
            else if (f<52){int j2=f-16; s[KO_BM+j2]=al0*sB[j2]+al1*sB[36+j2]+al2*sB[72+j2];}
            else          {int j2=f-52; s[KO_CM+j2]=al0*sC[j2]+al1*sC[32+j2]+al2*sC[64+j2];}
        }
        __syncwarp();
        // ---- P2: predict mu, T=Am*Sig ; CtC -> MM ----
        if (t==0){
            if (ln<4) s[KO_MUP+ln]=0.f;
            if (ln>=16){int l=ln-16; s[KO_SIGP+l]=((l>>2)==(l&3))?20.f:0.f;}
        } else {
            if (ln<4){
                float v=0.f;
#pragma unroll
                for (int j=0;j<4;j++) v += s[KO_AM+ln*4+j]*s[KO_MU+j];
#pragma unroll
                for (int j=0;j<9;j++) v += s[KO_BM+ln*9+j]*s[KO_UT+j];
                s[KO_MUP+ln]=v;
            }
            if (ln>=16){
                int l=ln-16, i=l>>2, j=l&3; float v=0.f;
#pragma unroll
                for (int k=0;k<4;k++) v += s[KO_AM+i*4+k]*s[KO_SIG+k*4+j];
                s[KO_T+l]=v;
            }
        }
        if (ln>=4 && ln<14){
            const int pi_[10]={0,0,0,0,1,1,1,2,2,3};
            const int pj_[10]={0,1,2,3,1,2,3,2,3,3};
            int l=ln-4, i=pi_[l], j=pj_[l];
            float v=0.f;
#pragma unroll
            for (int cc=0;cc<8;cc++) v += s[KO_CM+cc*4+i]*s[KO_CM+cc*4+j];
            v*=ir;
            s[KO_MM+i*4+j]=v; s[KO_MM+j*4+i]=v;
        }
        __syncwarp();
        // ---- P3: Sig_p = T*Am^T + Q ----
        if (t>0 && ln<16){
            int i=ln>>2, j=ln&3;
            float v=(i==j)?qn:0.f;
#pragma unroll
            for (int k=0;k<4;k++) v += s[KO_T+i*4+k]*s[KO_AM+j*4+k];
            s[KO_SIGP+ln]=v;
        }
        __syncwarp();
        // ---- P4: adj(Sig_p), 1/det(Sig_p); T2 = Sig_f_prev * Am^T ----
        if (ln<16) s[KO_PADJ+ln]=adj_entry(s+KO_SIGP, ln);
        if (ln==0) s[KO_DET]=1.f/det4s(s+KO_SIGP);
        if (t>0 && ln>=16){
            int l=ln-16, i=l>>2, j=l&3; float v=0.f;
#pragma unroll
            for (int k=0;k<4;k++) v += s[KO_SIG+i*4+k]*s[KO_AM+j*4+k];
            s[KO_T2+l]=v;
        }
        __syncwarp();
        // ---- P5: M = Pinv + CtC/r ; J_{t-1} = T2 * Pinv -> global ----
        {
            float idet=s[KO_DET];
            if (ln<16) s[KO_MM+ln] = s[KO_MM+ln] + s[KO_PADJ+ln]*idet;
            if (t>0 && ln>=16){
                int l=ln-16, i=l>>2, j=l&3; float v=0.f;
#pragma unroll
                for (int k=0;k<4;k++) v += s[KO_T2+i*4+k]*s[KO_PADJ+k*4+j];
                Jg[(bt-1)*16 + l] = v*idet;
            }
        }
        __syncwarp();
        // ---- P6: adj(M), 1/det(M); res = a - C mu_p ----
        if (ln<16) s[KO_MADJ+ln]=adj_entry(s+KO_MM, ln);
        if (ln==16) s[KO_DET+1]=1.f/det4s(s+KO_MM);
        if (ln>=20 && ln<28){
            int ri=ln-20; float v=s[KO_AT+ri];
#pragma unroll
            for (int k=0;k<4;k++) v -= s[KO_CM+ri*4+k]*s[KO_MUP+k];
            s[KO_RES+ri]=v;
        }
        __syncwarp();
        // ---- P7: Kg = Minv C^T / r  (Woodbury) ----
        {
            float idet2=s[KO_DET+1];
            int i=ln>>3, cc=ln&7;
            float v=0.f;
#pragma unroll
            for (int k=0;k<4;k++) v += s[KO_MADJ+i*4+k]*s[KO_CM+cc*4+k];
            s[KO_KG+i*8+cc]=v*idet2*ir;
        }
        __syncwarp();
        // ---- P8: mu_f ; stores ; IKC = I - Kg C ----
        if (ln<4){
            float v=s[KO_MUP+ln];
#pragma unroll
            for (int cc=0;cc<8;cc++) v += s[KO_KG+ln*8+cc]*s[KO_RES+cc];
            s[KO_MU+ln]=v;
            mu_f_g[bt*4+ln]=v;
        }
        if (ln>=4 && ln<8) mu_p_g[bt*4+ln-4]=s[KO_MUP+ln-4];
        if (ln>=8 && ln<24){
            int l=ln-8, i=l>>2, j=l&3;
            float v=(i==j)?1.f:0.f;
#pragma unroll
            for (int cc=0;cc<8;cc++) v -= s[KO_KG+i*8+cc]*s[KO_CM+cc*4+j];
            s[KO_IKC+l]=v;
        }
        __syncwarp();
        // ---- P9: T = IKC*Sig_p ; T2 = Kg Kg^T ----
        if (ln<16){
            int i=ln>>2, j=ln&3; float v=0.f;
#pragma unroll
            for (int k=0;k<4;k++) v += s[KO_IKC+i*4+k]*s[KO_SIGP+k*4+j];
            s[KO_T+ln]=v;
        } else {
            int l=ln-16, i=l>>2, j=l&3; float v=0.f;
#pragma unroll
            for (int cc=0;cc<8;cc++) v += s[KO_KG+i*8+cc]*s[KO_KG+j*8+cc];
            s[KO_T2+l]=v;
        }
        __syncwarp();
        // ---- P10: Sig_f = T*IKC^T + r*KgKg^T (Joseph) ----
        if (ln<16){
            int i=ln>>2, j=ln&3;
            float v=rn*s[KO_T2+ln];
#pragma unroll
            for (int k=0;k<4;k++) v += s[KO_T+i*4+k]*s[KO_IKC+j*4+k];
            s[KO_SIG+ln]=v;
        }
        __syncwarp();
    }
}

// ---------------- backward mu_smooth recursion (4 lanes per batch, prefetched) ------
__global__ __launch_bounds__(32)
void smooth_kernel(const float* __restrict__ mu_f, const float* __restrict__ mu_p,
                   const float* __restrict__ Jg, float* __restrict__ mus)
{
    int tid = threadIdx.x;
    int g = blockIdx.x*8 + (tid>>2);
    int i = tid & 3;
    size_t base = (size_t)g*TT_;
    float v = mu_f[(base+TT_-1)*4 + i];
    mus[(base+TT_-1)*4 + i] = v;
    unsigned gb = tid & ~3u;
    float4 Jr = *(const float4*)&Jg[(base+TT_-2)*16 + i*4];
    float mf = mu_f[(base+TT_-2)*4 + i];
    float mp = mu_p[(base+TT_-1)*4 + i];
    for (int t=TT_-2; t>=0; t--){
        float4 Jn; float mfn=0.f, mpn=0.f;
        if (t>0){
            Jn  = *(const float4*)&Jg[(base+t-1)*16 + i*4];
            mfn = mu_f[(base+t-1)*4 + i];
            mpn = mu_p[(base+t)*4 + i];
        } else { Jn = Jr; }
        float mi = v - mp;
        float m0=__shfl_sync(0xffffffffu, mi, gb+0);
        float m1=__shfl_sync(0xffffffffu, mi, gb+1);
        float m2=__shfl_sync(0xffffffffu, mi, gb+2);
        float m3=__shfl_sync(0xffffffffu, mi, gb+3);
        v = mf + Jr.x*m0 + Jr.y*m1 + Jr.z*m2 + Jr.w*m3;
        mus[(base+t)*4+i]=v;
        Jr=Jn; mf=mfn; mp=mpn;
    }
}

// ---------------- a_hat = C_mix mu_smooth -------------------------------------------
__global__ void ahat_kernel(const float* __restrict__ alpha, const float* __restrict__ mus,
                            const float* __restrict__ Cg, float* __restrict__ ahat)
{
    int idx = blockIdx.x*blockDim.x + threadIdx.x;
    if (idx >= NROWS) return;
    float a0=alpha[(size_t)idx*3+0], a1=alpha[(size_t)idx*3+1], a2=alpha[(size_t)idx*3+2];
    float4 mu = *(const float4*)&mus[(size_t)idx*4];
    float mv[4]={mu.x,mu.y,mu.z,mu.w};
#pragma unroll
    for (int r=0;r<8;r++){
        float v=0.f;
#pragma unroll
        for (int j=0;j<4;j++){
            float cm = a0*__ldg(&Cg[r*4+j]) + a1*__ldg(&Cg[32+r*4+j]) + a2*__ldg(&Cg[64+r*4+j]);
            v += cm*mv[j];
        }
        ahat[(size_t)idx*8+r]=v;
    }
}

// ---------------- decoder layer 1: d1 = tanh(ahat @ W^T + b) (K=8) ------------------
__global__ __launch_bounds__(256)
void dec1_kernel(const float* __restrict__ ahat, const float* __restrict__ W,
                 const float* __restrict__ bvec, float* __restrict__ out)
{
    __shared__ float sa[16][8];
    int tid = threadIdx.x;
    int r0 = blockIdx.x*16;
    if (tid<128) sa[tid>>3][tid&7] = ahat[(size_t)r0*8 + tid];
    int n = tid & 127;
    float w[8];
#pragma unroll
    for (int j=0;j<8;j++) w[j]=W[n*8+j];
    float bb=bvec[n];
    __syncthreads();
    int half = tid>>7;
#pragma unroll
    for (int q=0;q<8;q++){
        int rl = half*8+q;
        float s=bb;
#pragma unroll
        for (int j=0;j<8;j++) s += sa[rl][j]*w[j];
        out[(size_t)(r0+rl)*128 + n] = tanhf(s);
    }
}

// ---------------- launcher ----------------------------------------------------------
extern "C" void kernel_launch(void* const* d_in, const int* in_sizes, int n_in,
                              void* d_out, int out_size)
{
    const float* x       = (const float*)d_in[0];
    const float* m       = (const float*)d_in[1];
    const float* u_ext   = (const float*)d_in[2];
    const float* eps     = (const float*)d_in[3];
    const float* enc_W1  = (const float*)d_in[4];
    const float* enc_b1  = (const float*)d_in[5];
    const float* enc_W2  = (const float*)d_in[6];
    const float* enc_b2  = (const float*)d_in[7];
    const float* W_mean  = (const float*)d_in[8];
    const float* b_mean  = (const float*)d_in[9];
    const float* Amat    = (const float*)d_in[10];
    const float* Bmat    = (const float*)d_in[11];
    const float* Cmat    = (const float*)d_in[12];
    const float* a_init  = (const float*)d_in[13];
    const float* lstm_Wih= (const float*)d_in[14];
    const float* lstm_Whh= (const float*)d_in[15];
    const float* lstm_bih= (const float*)d_in[16];
    const float* lstm_bhh= (const float*)d_in[17];
    const float* alpha_W = (const float*)d_in[18];
    const float* alpha_b = (const float*)d_in[19];
    const float* dec_W1  = (const float*)d_in[20];
    const float* dec_b1  = (const float*)d_in[21];
    const float* dec_W2  = (const float*)d_in[22];
    const float* dec_b2  = (const float*)d_in[23];
    const float* gen_W   = (const float*)d_in[24];
    const float* gen_b   = (const float*)d_in[25];

    float *p_buf1,*p_buf2,*p_a,*p_alpha,*p_mup,*p_muf,*p_J,*p_mus,*p_ahat;
    cudaGetSymbolAddress((void**)&p_buf1,  g_buf1);
    cudaGetSymbolAddress((void**)&p_buf2,  g_buf2);
    cudaGetSymbolAddress((void**)&p_a,     g_a);
    cudaGetSymbolAddress((void**)&p_alpha, g_alpha);
    cudaGetSymbolAddress((void**)&p_mup,   g_mup);
    cudaGetSymbolAddress((void**)&p_muf,   g_muf);
    cudaGetSymbolAddress((void**)&p_J,     g_J);
    cudaGetSymbolAddress((void**)&p_mus,   g_mus);
    cudaGetSymbolAddress((void**)&p_ahat,  g_ahat);

    // encoder
    sgemm128<1,true ><<<NROWS/128,256>>>(x, m, enc_W1, enc_b1, p_buf1, 256);
    sgemm128<1,false><<<NROWS/128,256>>>(p_buf1, nullptr, enc_W2, enc_b2, p_buf2, 128);
    enc3_kernel<<<NROWS/32,256>>>(p_buf2, W_mean, b_mean, eps, p_a);
    // LSTM -> alpha
    lstm_kernel<<<BSZ,256>>>(p_a, a_init, lstm_Wih, lstm_Whh, lstm_bih, lstm_bhh,
                             alpha_W, alpha_b, p_alpha);
    // Kalman forward (+ fused smoother gains J)
    kf_forward<<<BSZ/2,64>>>(p_alpha, p_a, a_init, u_ext, Amat, Bmat, Cmat,
                             p_mup, p_muf, p_J);
    // backward mu recursion
    smooth_kernel<<<32,32>>>(p_muf, p_mup, p_J, p_mus);
    ahat_kernel<<<NROWS/256,256>>>(p_alpha, p_mus, Cmat, p_ahat);
    // decoder
    dec1_kernel<<<NROWS/16,256>>>(p_ahat, dec_W1, dec_b1, p_buf1);
    sgemm128<1,false><<<NROWS/128,256>>>(p_buf1, nullptr, dec_W2, dec_b2, p_buf2, 128);
    sgemm128<2,false><<<NROWS/128,256>>>(p_buf2, nullptr, gen_W, gen_b, (float*)d_out, 128);
    (void)in_sizes; (void)n_in; (void)out_size;
}

// round 3
// speedup vs baseline: 1.9404x; 1.0647x over previous
#include <cuda_runtime.h>
#include <math.h>
#include <stdint.h>

#define BSZ 256
#define TT_ 512
#define ADIM 8
#define ZDIM 4
#define KMIX 3
#define HL 50
#define HID 128
#define NROWS (BSZ*TT_)

// ---------------- scratch (static __device__; cudaMalloc forbidden) ----------------
__device__ float g_buf1[NROWS*HID];
__device__ float g_buf2[NROWS*HID];
__device__ float g_a[NROWS*ADIM];
__device__ float g_alpha[NROWS*KMIX];
__device__ float g_mup[NROWS*ZDIM];
__device__ float g_muf[NROWS*ZDIM];
__device__ float g_J[NROWS*ZDIM*ZDIM];
__device__ float g_mus[NROWS*ZDIM];
__device__ float g_ahat[NROWS*ADIM];

// ---------------- fast activations (EX2/RCP MUFU based; rel err ~1e-7) -------------
__device__ __forceinline__ float fsig(float x){
    return __fdividef(1.f, 1.f + __expf(-x));
}
__device__ __forceinline__ float ftanh(float x){
    float xc = fminf(fmaxf(x, -15.f), 15.f);
    float t = __expf(2.f*xc);
    return __fdividef(t-1.f, t+1.f);
}

template<int ACT>
__device__ __forceinline__ float actf(float v){
    if (ACT == 1) return ftanh(v);
    if (ACT == 2) return fsig(v);
    return v;
}

// ---------------- generic fused SGEMM: C[M,128] = act(A[M,K] @ W[128,K]^T + bias) ----
template<int ACT, bool CONCAT>
__global__ __launch_bounds__(256,2)
void sgemm128(const float* __restrict__ A0, const float* __restrict__ A1,
              const float* __restrict__ W, const float* __restrict__ bias,
              float* __restrict__ C, int K)
{
    __shared__ __align__(16) float As[16][132];
    __shared__ __align__(16) float Bsm[16][132];
    const int tid = threadIdx.x;
    const int row0 = blockIdx.x * 128;
    const int tx = tid & 15, ty = tid >> 4;
    float acc[8][8];
#pragma unroll
    for (int i=0;i<8;i++)
#pragma unroll
        for (int j=0;j<8;j++) acc[i][j]=0.f;

    for (int k0=0;k0<K;k0+=16){
#pragma unroll
        for (int q=tid;q<512;q+=256){
            int r=q>>2, kc=(q&3)<<2;
            const float* src;
            if (CONCAT){
                int gk=k0+kc;
                src = (gk<128)? (A0 + (size_t)(row0+r)*128 + gk)
                              : (A1 + (size_t)(row0+r)*128 + (gk-128));
            } else {
                src = A0 + (size_t)(row0+r)*K + k0 + kc;
            }
            float4 v = *(const float4*)src;
            As[kc+0][r]=v.x; As[kc+1][r]=v.y; As[kc+2][r]=v.z; As[kc+3][r]=v.w;
        }
#pragma unroll
        for (int q=tid;q<512;q+=256){
            int n=q>>2, kc=(q&3)<<2;
            float4 v = *(const float4*)(W + (size_t)n*K + k0 + kc);
            Bsm[kc+0][n]=v.x; Bsm[kc+1][n]=v.y; Bsm[kc+2][n]=v.z; Bsm[kc+3][n]=v.w;
        }
        __syncthreads();
#pragma unroll
        for (int k=0;k<16;k++){
            float4 a0=*(const float4*)&As[k][ty*8];
            float4 a1=*(const float4*)&As[k][ty*8+4];
            float4 b0=*(const float4*)&Bsm[k][tx*8];
            float4 b1=*(const float4*)&Bsm[k][tx*8+4];
            float av[8]={a0.x,a0.y,a0.z,a0.w,a1.x,a1.y,a1.z,a1.w};
            float bv[8]={b0.x,b0.y,b0.z,b0.w,b1.x,b1.y,b1.z,b1.w};
#pragma unroll
            for (int i=0;i<8;i++)
#pragma unroll
                for (int j=0;j<8;j++)
                    acc[i][j] += av[i]*bv[j];
        }
        __syncthreads();
    }
    float bn[8];
#pragma unroll
    for (int j=0;j<8;j++) bn[j]=bias[tx*8+j];
#pragma unroll
    for (int i=0;i<8;i++){
        size_t gr = (size_t)row0 + ty*8 + i;
        float4 o0, o1;
        o0.x=actf<ACT>(acc[i][0]+bn[0]); o0.y=actf<ACT>(acc[i][1]+bn[1]);
        o0.z=actf<ACT>(acc[i][2]+bn[2]); o0.w=actf<ACT>(acc[i][3]+bn[3]);
        o1.x=actf<ACT>(acc[i][4]+bn[4]); o1.y=actf<ACT>(acc[i][5]+bn[5]);
        o1.z=actf<ACT>(acc[i][6]+bn[6]); o1.w=actf<ACT>(acc[i][7]+bn[7]);
        *(float4*)&C[gr*128 + tx*8]     = o0;
        *(float4*)&C[gr*128 + tx*8 + 4] = o1;
    }
}

// ---------------- encoder layer 3: a = Y2 @ Wm^T + bm + eps  (N=8, K=128) ----------
__global__ __launch_bounds__(256)
void enc3_kernel(const float* __restrict__ Y2, const float* __restrict__ Wm,
                 const float* __restrict__ bm, const float* __restrict__ eps,
                 float* __restrict__ aout)
{
    __shared__ __align__(16) float sW[8][128];
    for (int i=threadIdx.x;i<1024;i+=256) sW[i>>7][i&127]=Wm[i];
    __syncthreads();
    int r = blockIdx.x*32 + (threadIdx.x>>3);
    int n = threadIdx.x&7;
    const float4* y = (const float4*)(Y2 + (size_t)r*128);
    const float4* w = (const float4*)&sW[n][0];
    float s=0.f;
#pragma unroll
    for (int k=0;k<32;k++){
        float4 yv=y[k], wv=w[k];
        s += yv.x*wv.x+yv.y*wv.y+yv.z*wv.z+yv.w*wv.w;
    }
    aout[(size_t)r*8+n] = s + bm[n] + eps[(size_t)r*8+n];
}

// ---------------- LSTM + alpha: block per batch, 2 syncs/step, pipelined alpha ------
__global__ __launch_bounds__(256)
void lstm_kernel(const float* __restrict__ a, const float* __restrict__ a_init,
                 const float* __restrict__ Wih, const float* __restrict__ Whh,
                 const float* __restrict__ bih, const float* __restrict__ bhh,
                 const float* __restrict__ aW, const float* __restrict__ ab,
                 float* __restrict__ alpha)
{
    __shared__ __align__(16) float4 shv[13];      // h, padded to 52
    __shared__ __align__(16) float4 sxv[2][2];    // x_t, double buffered (8)
    __shared__ float spre[200];
    __shared__ __align__(16) float4 saWv[3][13];
    __shared__ float sab_s[3];
    __shared__ float slog[3];
    int tid=threadIdx.x; int b=blockIdx.x;

    float wih[8], whh[52], bsum=0.f, c=0.f;
    if (tid<200){
#pragma unroll
        for (int j=0;j<8;j++) wih[j]=Wih[tid*8+j];
#pragma unroll
        for (int j=0;j<50;j++) whh[j]=Whh[tid*50+j];
        whh[50]=0.f; whh[51]=0.f;
        bsum = bih[tid]+bhh[tid];
    }
    for (int i=tid;i<3*52;i+=256){
        int row=i/52, col=i%52;
        ((float*)saWv)[i] = (col<50)? aW[row*50+col] : 0.f;
    }
    if (tid<3) sab_s[tid]=ab[tid];
    for (int i=tid;i<52;i+=256) ((float*)shv)[i]=0.f;
    if (tid<8) ((float*)sxv)[tid]=a_init[tid];    // sxv[0] = a_init
    __syncthreads();

    for (int t=0;t<TT_;t++){
        int pb = t&1;
        // ---- P1 ----
        if (tid<200){
            const float4* xv = sxv[pb];
            float4 x0=xv[0], x1=xv[1];
            float a0 = bsum + wih[0]*x0.x + wih[4]*x1.x;
            float a1 = wih[1]*x0.y + wih[5]*x1.y;
            float a2 = wih[2]*x0.z + wih[6]*x1.z;
            float a3 = wih[3]*x0.w + wih[7]*x1.w;
#pragma unroll
            for (int q=0;q<13;q++){
                float4 hv=shv[q];
                a0 += whh[4*q+0]*hv.x;
                a1 += whh[4*q+1]*hv.y;
                a2 += whh[4*q+2]*hv.z;
                a3 += whh[4*q+3]*hv.w;
            }
            spre[tid]=(a0+a1)+(a2+a3);
        } else if (tid>=224 && tid<227){
            if (t>0){
                int k=tid-224;
                float a0=0,a1=0,a2=0,a3=0;
#pragma unroll
                for (int q=0;q<13;q++){
                    float4 wv=saWv[k][q], hv=shv[q];
                    a0+=wv.x*hv.x; a1+=wv.y*hv.y; a2+=wv.z*hv.z; a3+=wv.w*hv.w;
                }
                slog[k]=(a0+a1)+(a2+a3)+sab_s[k];
            }
        } else if (tid>=232 && tid<240){
            if (t<TT_-1)
                ((float*)sxv[pb^1])[tid-232] = a[((size_t)b*TT_+t)*8 + (tid-232)];
        }
        __syncthreads();
        // ---- P2 ----
        if (tid<50){
            float pi=spre[tid], pf=spre[50+tid], pg=spre[100+tid], po=spre[150+tid];
            float ig=fsig(pi);
            float fg=fsig(pf);
            float gg=ftanh(pg);
            float og=fsig(po);
            c = fg*c + ig*gg;
            ((float*)shv)[tid] = og*ftanh(c);
        } else if (tid>=224 && tid<227 && t>0){
            int k=tid-224;
            float l0=slog[0],l1=slog[1],l2=slog[2];
            float mx=fmaxf(l0,fmaxf(l1,l2));
            float e0=__expf(l0-mx),e1=__expf(l1-mx),e2=__expf(l2-mx);
            float inv=__fdividef(1.f, e0+e1+e2);
            float mine=(k==0)?e0:((k==1)?e1:e2);
            alpha[((size_t)b*TT_+t-1)*3+k]=mine*inv;
        }
        __syncthreads();
    }
    // final alpha (t = T-1) from h_{T-1}
    if (tid>=224 && tid<227){
        int k=tid-224;
        float lg[3];
#pragma unroll
        for (int kk=0;kk<3;kk++){
            float a0=0,a1=0,a2=0,a3=0;
#pragma unroll
            for (int q=0;q<13;q++){
                float4 wv=saWv[kk][q], hv=shv[q];
                a0+=wv.x*hv.x; a1+=wv.y*hv.y; a2+=wv.z*hv.z; a3+=wv.w*hv.w;
            }
            lg[kk]=(a0+a1)+(a2+a3)+sab_s[kk];
        }
        float mx=fmaxf(lg[0],fmaxf(lg[1],lg[2]));
        float e0=__expf(lg[0]-mx),e1=__expf(lg[1]-mx),e2=__expf(lg[2]-mx);
        float inv=__fdividef(1.f, e0+e1+e2);
        float mine=(k==0)?e0:((k==1)?e1:e2);
        alpha[((size_t)b*TT_+TT_-1)*3+k]=mine*inv;
    }
}

// ---------------- 4x4 determinant + adjugate helpers --------------------------------
__device__ __forceinline__ float det4s(const float* m){
    float m00=m[0],m01=m[1],m02=m[2],m03=m[3];
    float m10=m[4],m11=m[5],m12=m[6],m13=m[7];
    float m20=m[8],m21=m[9],m22=m[10],m23=m[11];
    float m30=m[12],m31=m[13],m32=m[14],m33=m[15];
    return m00*(m11*(m22*m33-m23*m32)-m12*(m21*m33-m23*m31)+m13*(m21*m32-m22*m31))
         - m01*(m10*(m22*m33-m23*m32)-m12*(m20*m33-m23*m30)+m13*(m20*m32-m22*m30))
         + m02*(m10*(m21*m33-m23*m31)-m11*(m20*m33-m23*m30)+m13*(m20*m31-m21*m30))
         - m03*(m10*(m21*m32-m22*m31)-m11*(m20*m32-m22*m30)+m12*(m20*m31-m21*m30));
}

// adjugate entry for inverse layout: INV[r*4+c] = cof(c,r);  inv = adj * (1/det)
__device__ __forceinline__ float adj_entry(const float* m, int l){
    int r=l>>2, c=l&3;
    int rr[3], cc[3];
    int p=0;
#pragma unroll
    for (int k=0;k<4;k++) if (k!=c) rr[p++]=k;
    p=0;
#pragma unroll
    for (int k=0;k<4;k++) if (k!=r) cc[p++]=k;
    float a00=m[rr[0]*4+cc[0]], a01=m[rr[0]*4+cc[1]], a02=m[rr[0]*4+cc[2]];
    float a10=m[rr[1]*4+cc[0]], a11=m[rr[1]*4+cc[1]], a12=m[rr[1]*4+cc[2]];
    float a20=m[rr[2]*4+cc[0]], a21=m[rr[2]*4+cc[1]], a22=m[rr[2]*4+cc[2]];
    float d = a00*(a11*a22-a12*a21) - a01*(a10*a22-a12*a20) + a02*(a10*a21-a11*a20);
    return ((r+c)&1)? -d : d;
}

// ---------------- Kalman forward + smoother gains (information form, 9 phases) -----
#define KO_AM   0
#define KO_BM   16
#define KO_CM   52
#define KO_SIG  84
#define KO_SIGP 100
#define KO_PADJ 116
#define KO_CTC  132
#define KO_N    148
#define KO_NADJ 164
#define KO_T2   180
#define KO_JT   196
#define KO_KG   212
#define KO_MU   244
#define KO_MUP  248
#define KO_RES  252
#define KO_AT   260
#define KO_UT   268
#define KO_AL   277
#define KO_SC   280
#define KWSZ    288

__global__ __launch_bounds__(64)
void kf_forward(const float* __restrict__ alpha, const float* __restrict__ a,
                const float* __restrict__ a_init, const float* __restrict__ u_ext,
                const float* __restrict__ Ag, const float* __restrict__ Bg,
                const float* __restrict__ Cg,
                float* __restrict__ mu_p_g, float* __restrict__ mu_f_g,
                float* __restrict__ Jg)
{
    __shared__ float sA[48], sB[108], sC[96];
    __shared__ float wsm[2][KWSZ];
    const float qn=0.08f, ir=1.f/0.03f;
    int w = threadIdx.x>>5, ln = threadIdx.x&31;
    int b = blockIdx.x*2 + w;
    for (int i=threadIdx.x;i<48;i+=64) sA[i]=Ag[i];
    for (int i=threadIdx.x;i<108;i+=64) sB[i]=Bg[i];
    for (int i=threadIdx.x;i<96;i+=64) sC[i]=Cg[i];
    __syncthreads();
    float* s = wsm[w];

    // prefetch t=0 inputs
    float r_al=0.f, r_a=0.f, r_u=0.f, r_ap=0.f;
    if (ln<3)            r_al = alpha[(size_t)b*TT_*3 + ln];
    if (ln>=4 && ln<12){ r_a  = a[(size_t)b*TT_*8 + (ln-4)]; r_ap = a_init[ln-4]; }
    if (ln==12)          r_u  = u_ext[(size_t)b*TT_];

    for (int t=0;t<TT_;t++){
        size_t bt = (size_t)b*TT_ + t;
        // ---- P0: publish step inputs ----
        if (ln<3) s[KO_AL+ln]=r_al;
        if (ln>=4 && ln<12){ s[KO_AT+ln-4]=r_a; s[KO_UT+ln-4]=r_ap; r_ap=r_a; }
        if (ln==12) s[KO_UT+8]=r_u;
        __syncwarp();
        // prefetch t+1 (hidden behind this step's compute)
        if (t+1<TT_){
            if (ln<3)            r_al = alpha[(bt+1)*3+ln];
            if (ln>=4 && ln<12)  r_a  = a[(bt+1)*8 + (ln-4)];
            if (ln==12)          r_u  = u_ext[bt+1];
        }
        // ---- P1: mix Am/Bm/Cm ----
        float al0=s[KO_AL], al1=s[KO_AL+1], al2=s[KO_AL+2];
        for (int f=ln; f<84; f+=32){
            if (f<16)      s[KO_AM+f] = al0*sA[f] + al1*sA[16+f] + al2*sA[32+f];
            else if (f<52){int j2=f-16; s[KO_BM+j2]=al0*sB[j2]+al1*sB[36+j2]+al2*sB[72+j2];}
            else          {int j2=f-52; s[KO_CM+j2]=al0*sC[j2]+al1*sC[32+j2]+al2*sC[64+j2];}
        }
        __syncwarp();
        // ---- P2: mu_p ; Sig_p (fused AmSigAm^T+Q) ; CtC/r ----
        if (t==0){
            if (ln<4) s[KO_MUP+ln]=0.f;
            if (ln>=16){int l=ln-16; s[KO_SIGP+l]=((l>>2)==(l&3))?20.f:0.f;}
        } else {
            if (ln<4){
                float v=0.f;
#pragma unroll
                for (int j=0;j<4;j++) v += s[KO_AM+ln*4+j]*s[KO_MU+j];
#pragma unroll
                for (int j=0;j<9;j++) v += s[KO_BM+ln*9+j]*s[KO_UT+j];
                s[KO_MUP+ln]=v;
            }
            if (ln>=16){
                int l=ln-16, i=l>>2, j=l&3;
                float v=(i==j)?qn:0.f;
#pragma unroll
                for (int k=0;k<4;k++){
                    float inner=0.f;
#pragma unroll
                    for (int q=0;q<4;q++) inner += s[KO_SIG+k*4+q]*s[KO_AM+j*4+q];
                    v += s[KO_AM+i*4+k]*inner;
                }
                s[KO_SIGP+l]=v;
            }
        }
        if (ln>=4 && ln<14){
            const int pi_[10]={0,0,0,0,1,1,1,2,2,3};
            const int pj_[10]={0,1,2,3,1,2,3,2,3,3};
            int l=ln-4, i=pi_[l], j=pj_[l];
            float v=0.f;
#pragma unroll
            for (int cc=0;cc<8;cc++) v += s[KO_CM+cc*4+i]*s[KO_CM+cc*4+j];
            v*=ir;
            s[KO_CTC+i*4+j]=v; s[KO_CTC+j*4+i]=v;
        }
        __syncwarp();
        // ---- P3: PADJ = adj(Sig_p) ; T2 = Sig_f_prev * Am^T ----
        if (ln<16) s[KO_PADJ+ln]=adj_entry(s+KO_SIGP, ln);
        else if (t>0){
            int l=ln-16, i=l>>2, j=l&3; float v=0.f;
#pragma unroll
            for (int k=0;k<4;k++) v += s[KO_SIG+i*4+k]*s[KO_AM+j*4+k];
            s[KO_T2+l]=v;
        }
        __syncwarp();
        // ---- P4: detP ; res = a - C mu_p ; JT = T2 * PADJ ----
        if (ln==0){
            float dp = s[KO_SIGP+0]*s[KO_PADJ+0] + s[KO_SIGP+1]*s[KO_PADJ+4]
                     + s[KO_SIGP+2]*s[KO_PADJ+8] + s[KO_SIGP+3]*s[KO_PADJ+12];
            s[KO_SC+0]=dp;
            s[KO_SC+1]=__fdividef(1.f,dp);
        }
        if (ln>=8 && ln<16){
            int cc=ln-8; float v=s[KO_AT+cc];
#pragma unroll
            for (int k=0;k<4;k++) v -= s[KO_CM+cc*4+k]*s[KO_MUP+k];
            s[KO_RES+cc]=v;
        }
        if (t>0 && ln>=16){
            int l=ln-16, i=l>>2, j=l&3; float v=0.f;
#pragma unroll
            for (int k=0;k<4;k++) v += s[KO_T2+i*4+k]*s[KO_PADJ+k*4+j];
            s[KO_JT+l]=v;
        }
        __syncwarp();
        // ---- P5: N = PADJ + detP*CtC/r ; J_{t-1} = JT*idetP -> global ----
        if (ln<16) s[KO_N+ln] = s[KO_PADJ+ln] + s[KO_SC+0]*s[KO_CTC+ln];
        else if (t>0){
            int l=ln-16;
            Jg[(bt-1)*16 + l] = s[KO_JT+l]*s[KO_SC+1];
        }
        __syncwarp();
        // ---- P6: NADJ = adj(N) ; detN (concurrent) ----
        if (ln<16) s[KO_NADJ+ln]=adj_entry(s+KO_N, ln);
        if (ln==16){
            float dn = det4s(s+KO_N);
            float sc = __fdividef(s[KO_SC+0], dn);   // detP/detN : Sig_f = NADJ*sc
            s[KO_SC+2]=sc;
            s[KO_SC+3]=sc*ir;                        // Kg scale
        }
        __syncwarp();
        // ---- P7: KGraw = NADJ * C^T (4x8, all 32 lanes) ----
        {
            int i=ln>>3, cc=ln&7; float v=0.f;
#pragma unroll
            for (int k=0;k<4;k++) v += s[KO_NADJ+i*4+k]*s[KO_CM+cc*4+k];
            s[KO_KG+i*8+cc]=v;
        }
        __syncwarp();
        // ---- P8: Sig_f = NADJ*sc ; mu_f = mu_p + sc*ir*KGraw*res ; stores ----
        if (ln>=16){
            int l=ln-16;
            s[KO_SIG+l]=s[KO_NADJ+l]*s[KO_SC+2];
        }
        if (ln<4){
            float acc=0.f;
#pragma unroll
            for (int cc=0;cc<8;cc++) acc += s[KO_KG+ln*8+cc]*s[KO_RES+cc];
            float v = s[KO_MUP+ln] + acc*s[KO_SC+3];
            s[KO_MU+ln]=v;
            mu_f_g[bt*4+ln]=v;
        }
        if (ln>=4 && ln<8) mu_p_g[bt*4+ln-4]=s[KO_MUP+ln-4];
        __syncwarp();
    }
}

// ---------------- backward mu_smooth recursion (4 lanes per batch, prefetched) ------
__global__ __launch_bounds__(32)
void smooth_kernel(const float* __restrict__ mu_f, const float* __restrict__ mu_p,
                   const float* __restrict__ Jg, float* __restrict__ mus)
{
    int tid = threadIdx.x;
    int g = blockIdx.x*8 + (tid>>2);
    int i = tid & 3;
    size_t base = (size_t)g*TT_;
    float v = mu_f[(base+TT_-1)*4 + i];
    mus[(base+TT_-1)*4 + i] = v;
    unsigned gb = tid & ~3u;
    float4 Jr = *(const float4*)&Jg[(base+TT_-2)*16 + i*4];
    float mf = mu_f[(base+TT_-2)*4 + i];
    float mp = mu_p[(base+TT_-1)*4 + i];
    for (int t=TT_-2; t>=0; t--){
        float4 Jn; float mfn=0.f, mpn=0.f;
        if (t>0){
            Jn  = *(const float4*)&Jg[(base+t-1)*16 + i*4];
            mfn = mu_f[(base+t-1)*4 + i];
            mpn = mu_p[(base+t)*4 + i];
        } else { Jn = Jr; }
        float mi = v - mp;
        float m0=__shfl_sync(0xffffffffu, mi, gb+0);
        float m1=__shfl_sync(0xffffffffu, mi, gb+1);
        float m2=__shfl_sync(0xffffffffu, mi, gb+2);
        float m3=__shfl_sync(0xffffffffu, mi, gb+3);
        v = mf + Jr.x*m0 + Jr.y*m1 + Jr.z*m2 + Jr.w*m3;
        mus[(base+t)*4+i]=v;
        Jr=Jn; mf=mfn; mp=mpn;
    }
}

// ---------------- a_hat = C_mix mu_smooth -------------------------------------------
__global__ void ahat_kernel(const float* __restrict__ alpha, const float* __restrict__ mus,
                            const float* __restrict__ Cg, float* __restrict__ ahat)
{
    int idx = blockIdx.x*blockDim.x + threadIdx.x;
    if (idx >= NROWS) return;
    float a0=alpha[(size_t)idx*3+0], a1=alpha[(size_t)idx*3+1], a2=alpha[(size_t)idx*3+2];
    float4 mu = *(const float4*)&mus[(size_t)idx*4];
    float mv[4]={mu.x,mu.y,mu.z,mu.w};
#pragma unroll
    for (int r=0;r<8;r++){
        float v=0.f;
#pragma unroll
        for (int j=0;j<4;j++){
            float cm = a0*__ldg(&Cg[r*4+j]) + a1*__ldg(&Cg[32+r*4+j]) + a2*__ldg(&Cg[64+r*4+j]);
            v += cm*mv[j];
        }
        ahat[(size_t)idx*8+r]=v;
    }
}

// ---------------- decoder layer 1: d1 = tanh(ahat @ W^T + b) (K=8) ------------------
__global__ __launch_bounds__(256)
void dec1_kernel(const float* __restrict__ ahat, const float* __restrict__ W,
                 const float* __restrict__ bvec, float* __restrict__ out)
{
    __shared__ float sa[16][8];
    int tid = threadIdx.x;
    int r0 = blockIdx.x*16;
    if (tid<128) sa[tid>>3][tid&7] = ahat[(size_t)r0*8 + tid];
    int n = tid & 127;
    float w[8];
#pragma unroll
    for (int j=0;j<8;j++) w[j]=W[n*8+j];
    float bb=bvec[n];
    __syncthreads();
    int half = tid>>7;
#pragma unroll
    for (int q=0;q<8;q++){
        int rl = half*8+q;
        float s=bb;
#pragma unroll
        for (int j=0;j<8;j++) s += sa[rl][j]*w[j];
        out[(size_t)(r0+rl)*128 + n] = ftanh(s);
    }
}

// ---------------- launcher ----------------------------------------------------------
extern "C" void kernel_launch(void* const* d_in, const int* in_sizes, int n_in,
                              void* d_out, int out_size)
{
    const float* x       = (const float*)d_in[0];
    const float* m       = (const float*)d_in[1];
    const float* u_ext   = (const float*)d_in[2];
    const float* eps     = (const float*)d_in[3];
    const float* enc_W1  = (const float*)d_in[4];
    const float* enc_b1  = (const float*)d_in[5];
    const float* enc_W2  = (const float*)d_in[6];
    const float* enc_b2  = (const float*)d_in[7];
    const float* W_mean  = (const float*)d_in[8];
    const float* b_mean  = (const float*)d_in[9];
    const float* Amat    = (const float*)d_in[10];
    const float* Bmat    = (const float*)d_in[11];
    const float* Cmat    = (const float*)d_in[12];
    const float* a_init  = (const float*)d_in[13];
    const float* lstm_Wih= (const float*)d_in[14];
    const float* lstm_Whh= (const float*)d_in[15];
    const float* lstm_bih= (const float*)d_in[16];
    const float* lstm_bhh= (const float*)d_in[17];
    const float* alpha_W = (const float*)d_in[18];
    const float* alpha_b = (const float*)d_in[19];
    const float* dec_W1  = (const float*)d_in[20];
    const float* dec_b1  = (const float*)d_in[21];
    const float* dec_W2  = (const float*)d_in[22];
    const float* dec_b2  = (const float*)d_in[23];
    const float* gen_W   = (const float*)d_in[24];
    const float* gen_b   = (const float*)d_in[25];

    float *p_buf1,*p_buf2,*p_a,*p_alpha,*p_mup,*p_muf,*p_J,*p_mus,*p_ahat;
    cudaGetSymbolAddress((void**)&p_buf1,  g_buf1);
    cudaGetSymbolAddress((void**)&p_buf2,  g_buf2);
    cudaGetSymbolAddress((void**)&p_a,     g_a);
    cudaGetSymbolAddress((void**)&p_alpha, g_alpha);
    cudaGetSymbolAddress((void**)&p_mup,   g_mup);
    cudaGetSymbolAddress((void**)&p_muf,   g_muf);
    cudaGetSymbolAddress((void**)&p_J,     g_J);
    cudaGetSymbolAddress((void**)&p_mus,   g_mus);
    cudaGetSymbolAddress((void**)&p_ahat,  g_ahat);

    // encoder
    sgemm128<1,true ><<<NROWS/128,256>>>(x, m, enc_W1, enc_b1, p_buf1, 256);
    sgemm128<1,false><<<NROWS/128,256>>>(p_buf1, nullptr, enc_W2, enc_b2, p_buf2, 128);
    enc3_kernel<<<NROWS/32,256>>>(p_buf2, W_mean, b_mean, eps, p_a);
    // LSTM -> alpha
    lstm_kernel<<<BSZ,256>>>(p_a, a_init, lstm_Wih, lstm_Whh, lstm_bih, lstm_bhh,
                             alpha_W, alpha_b, p_alpha);
    // Kalman forward (+ fused smoother gains J, information-form covariance)
    kf_forward<<<BSZ/2,64>>>(p_alpha, p_a, a_init, u_ext, Amat, Bmat, Cmat,
                             p_mup, p_muf, p_J);
    // backward mu recursion
    smooth_kernel<<<32,32>>>(p_muf, p_mup, p_J, p_mus);
    ahat_kernel<<<NROWS/256,256>>>(p_alpha, p_mus, Cmat, p_ahat);
    // decoder
    dec1_kernel<<<NROWS/16,256>>>(p_ahat, dec_W1, dec_b1, p_buf1);
    sgemm128<1,false><<<NROWS/128,256>>>(p_buf1, nullptr, dec_W2, dec_b2, p_buf2, 128);
    sgemm128<2,false><<<NROWS/128,256>>>(p_buf2, nullptr, gen_W, gen_b, (float*)d_out, 128);
    (void)in_sizes; (void)n_in; (void)out_size;
}